// round 15
// baseline (speedup 1.0000x reference)
#include <cuda_runtime.h>
#include <cuda_fp16.h>
#include <cstdint>

#define N_ATOMS 8000
#define N_PAIRS 80000
#define NF 32
#define GN_EPS 1e-5f

#define NB 444            // 3 CTAs/SM x 148 SMs: all resident in wave 1
#define NT 256
#define NWARPS_TOT (NB * 8)

// Scratch (device globals: no allocation allowed)
// A-table fp16, o-major: A2[a*256 + o*8 + q] = half2( A[a,2q,o], A[a,2q+1,o] )
__device__ __align__(16) uint32_t g_A2[(size_t)N_ATOMS * 256];
// fp16 sense: sense2[p*8 + q] = half2( sense[p,2q], sense[p,2q+1] )
__device__ __align__(16) uint32_t g_sense2[(size_t)N_PAIRS * 8];
__device__ __align__(16) float g_self[(size_t)N_ATOMS * NF];
__device__ int g_seg[N_ATOMS + 1];
__device__ int g_ctrB;                 // dynamic atom counter for phase B

// Grid barrier state: monotonic across launches (deterministic, no reset).
__device__ unsigned long long g_arrive = 0;
__device__ volatile unsigned long long g_release = 0;

__device__ __forceinline__ void grid_barrier() {
    __syncthreads();
    if (threadIdx.x == 0) {
        __threadfence();
        unsigned long long t = atomicAdd(&g_arrive, 1ULL) + 1ULL;
        unsigned long long target = ((t + NB - 1) / NB) * NB;
        if (t == target) {
            g_release = target;
        } else {
            while (g_release < target) __nanosleep(64);   // fixed: no backoff
        }
        __threadfence();
    }
    __syncthreads();
}

__device__ __forceinline__ float warp_sum(float v) {
#pragma unroll
    for (int off = 16; off; off >>= 1)
        v += __shfl_xor_sync(0xffffffffu, v, off);
    return v;
}

// A row gather: 2x LDG.128 (lane = o), 32B per lane
__device__ __forceinline__ void loadA2(uint4& u0, uint4& u1, int j, int lane) {
    const uint4* base = (const uint4*)(g_A2 + (size_t)j * 256 + lane * 8);
    u0 = __ldg(base);
    u1 = __ldg(base + 1);
}

__global__ void __launch_bounds__(NT, 3) k_fused(
    const float* __restrict__ feat,     // (N,32)
    const float* __restrict__ rhats,    // (P,4)
    const float* __restrict__ dist,     // (P,)
    const float* __restrict__ Wint,     // (16,32,32) d,o,f
    const float* __restrict__ sw,       // (32,32) o,f
    const float* __restrict__ sb,       // (32,)
    const float* __restrict__ mw,       // (64,32)
    const float* __restrict__ gnw,      // (64,)
    const float* __restrict__ gnb,      // (64,)
    const float* __restrict__ mu,       // (16,)
    const float* __restrict__ sg,       // (16,)
    const int*   __restrict__ pf,       // (P,)  sorted
    const int*   __restrict__ psec,     // (P,)
    float* __restrict__ out)            // (N,32)
{
    __shared__ __align__(16) float swT[NF * NF];       // selfint weights^T (4KB)
    __shared__ __align__(16) float msh[64 * NF];       // mixing weights (8KB)
    __shared__ __align__(16) float fsh[8 * NF];        // feat staging (1KB)
    __shared__ __align__(16) uint32_t WTs[32 * 257];   // fp16 Wint^T pad (33KB)

    const int tid  = threadIdx.x;
    const int bid  = blockIdx.x;
    const int lane = tid & 31;
    const int wid  = tid >> 5;
    const int gtid  = bid * NT + tid;
    const int gwarp = bid * 8 + wid;

    // per-lane constants
    const float mu_l  = mu[lane & 15];
    const float isg_l = 1.0f / sg[lane & 15];
    const float gw0 = gnw[lane],      gb0 = gnb[lane];
    const float gw1 = gnw[32 + lane], gb1 = gnb[32 + lane];

    // ======================= PHASE A (block-local; no internal barrier) =====
    if (gtid == 0) g_ctrB = 0;         // reset dynamic counter (barrier-ordered)

    // stage smem tables (all coalesced)
    for (int i = tid; i < 64 * NF; i += NT) msh[i] = mw[i];
    for (int i = tid; i < NF * NF; i += NT) {
        int o = i >> 5, f = i & 31;
        swT[f * NF + o] = sw[i];
    }
    // per-block transposed fp16 weight table: WTs[f*257 + q*32+o]
    {
#pragma unroll
        for (int cc = 0; cc < 32; ++cc) {
            float wa = Wint[(2 * wid) * (NF * NF) + cc * NF + lane];
            float wb = Wint[(2 * wid + 1) * (NF * NF) + cc * NF + lane];
            __half2 h2 = __floats2half2_rn(wa, wb);
            WTs[lane * 257 + wid * 32 + cc] = *reinterpret_cast<uint32_t*>(&h2);
        }
    }
    __syncthreads();

    // A.seg: segment starts via scatter on sorted pair_first
    for (int p = gtid; p < N_PAIRS; p += NB * NT) {
        int cur  = pf[p];
        int prev = (p == 0) ? -1 : pf[p - 1];
        for (int a = prev + 1; a <= cur; ++a) g_seg[a] = p;
        if (p == N_PAIRS - 1)
            for (int a = cur + 1; a <= N_ATOMS; ++a) g_seg[a] = N_PAIRS;
    }

    // A.sense: fp16 sense table, warp-cooperative. lane = h*16 + d, pair pb+h.
    {
        const int h = lane >> 4;
        const int d = lane & 15;
        for (int pb = gwarp * 2; pb < N_PAIRS; pb += NWARPS_TOT * 2) {
            const float dd = dist[pb + h];
            const float invd = 1.0f / dd;
            float cut = 0.f;
            if (dd < 6.5f) {
                float cc = cospif(dd * (0.5f / 6.5f));
                cut = cc * cc;
            }
            float t = (invd - mu_l) * isg_l;
            float e = cut * __expf(-0.5f * t * t);
            float e_hi = __shfl_xor_sync(0xffffffffu, e, 1);  // partner d^1
            if ((d & 1) == 0) {
                __half2 h2 = __floats2half2_rn(e, e_hi);
                g_sense2[(size_t)pb * 8 + h * 8 + (d >> 1)] =
                    *reinterpret_cast<uint32_t*>(&h2);
            }
        }
    }

    // A.self: self-interaction (fp32)
    for (int idx = gtid; idx < N_ATOMS * NF; idx += NB * NT) {
        int a = idx >> 5, o = idx & 31;
        float s = sb[o];
        const float* fr = feat + (size_t)a * NF;
#pragma unroll
        for (int f = 0; f < NF; ++f)
            s = fmaf(fr[f], swT[f * NF + o], s);
        g_self[idx] = s;
    }

    // A.gemm: A-table, 8-atom tiles, weights from smem WTs; o-major store
    {
        const int c = wid * 32 + lane;       // q = wid, o = lane
        const float4* fsh4 = (const float4*)fsh;
        for (int tile = bid; tile < N_ATOMS / 8; tile += NB) {
            const int a0 = tile * 8;
            __syncthreads();
            fsh[tid] = feat[(size_t)a0 * NF + tid];
            __syncthreads();
            float accA[8], accB[8];
#pragma unroll
            for (int k = 0; k < 8; ++k) { accA[k] = 0.f; accB[k] = 0.f; }
#pragma unroll
            for (int f4 = 0; f4 < 8; ++f4) {
                float2 wf[4];
#pragma unroll
                for (int t = 0; t < 4; ++t) {
                    uint32_t w2 = WTs[(4 * f4 + t) * 257 + c];
                    wf[t] = __half22float2(*reinterpret_cast<__half2*>(&w2));
                }
#pragma unroll
                for (int k = 0; k < 8; ++k) {
                    float4 v = fsh4[k * 8 + f4];
                    accA[k] = fmaf(v.x, wf[0].x, accA[k]);
                    accB[k] = fmaf(v.x, wf[0].y, accB[k]);
                    accA[k] = fmaf(v.y, wf[1].x, accA[k]);
                    accB[k] = fmaf(v.y, wf[1].y, accB[k]);
                    accA[k] = fmaf(v.z, wf[2].x, accA[k]);
                    accB[k] = fmaf(v.z, wf[2].y, accB[k]);
                    accA[k] = fmaf(v.w, wf[3].x, accA[k]);
                    accB[k] = fmaf(v.w, wf[3].y, accB[k]);
                }
            }
#pragma unroll
            for (int k = 0; k < 8; ++k) {
                __half2 h2 = __floats2half2_rn(accA[k], accB[k]);
                g_A2[(size_t)(a0 + k) * 256 + lane * 8 + wid] =
                    *reinterpret_cast<uint32_t*>(&h2);
            }
        }
    }

    grid_barrier();    // the ONLY grid barrier

    // ============================ PHASE B ===================================
    // DYNAMIC warp-per-atom (grab-ahead), even/odd double buffer.
    int a;
    if (lane == 0) a = atomicAdd(&g_ctrB, 1);
    a = __shfl_sync(0xffffffffu, a, 0);

    while (a < N_ATOMS) {
        int an;
        if (lane == 0) an = atomicAdd(&g_ctrB, 1);   // grab next early

        const int p0 = g_seg[a];
        const int n  = g_seg[a + 1] - p0;

        float acc0 = 0.f, acc1 = 0.f, acc2 = 0.f, acc3 = 0.f;

        auto process_pair = [&](const uint4& u0, const uint4& u1, int p) {
            const uint4* sp = (const uint4*)(g_sense2 + 8 * (size_t)p);
            uint4 s0 = __ldg(sp);
            uint4 s1 = __ldg(sp + 1);
            const float4 rh = *(const float4*)(rhats + 4 * (size_t)p);
            float dA = 0.f, dB = 0.f;
            {
                const uint32_t* sv = (const uint32_t*)&s0;
                const uint32_t* av = (const uint32_t*)&u0;
#pragma unroll
                for (int q = 0; q < 4; ++q) {
                    float2 fs = __half22float2(*(const __half2*)(&sv[q]));
                    float2 fa = __half22float2(*(const __half2*)(&av[q]));
                    dA = fmaf(fs.x, fa.x, dA);
                    dB = fmaf(fs.y, fa.y, dB);
                }
            }
            {
                const uint32_t* sv = (const uint32_t*)&s1;
                const uint32_t* av = (const uint32_t*)&u1;
#pragma unroll
                for (int q = 0; q < 4; ++q) {
                    float2 fs = __half22float2(*(const __half2*)(&sv[q]));
                    float2 fa = __half22float2(*(const __half2*)(&av[q]));
                    dA = fmaf(fs.x, fa.x, dA);
                    dB = fmaf(fs.y, fa.y, dB);
                }
            }
            const float wgt = dA + dB;
            acc0 = fmaf(rh.x, wgt, acc0);
            acc1 = fmaf(rh.y, wgt, acc1);
            acc2 = fmaf(rh.z, wgt, acc2);
            acc3 = fmaf(rh.w, wgt, acc3);
        };

        if (n > 0) {
            uint4 b00, b01, b10, b11;
            loadA2(b00, b01, psec[p0], lane);
            if (n > 1) loadA2(b10, b11, psec[p0 + 1], lane);
            int jn = (n > 2) ? psec[p0 + 2] : 0;
            int i = 0;
            for (;;) {
                process_pair(b00, b01, p0 + i);
                if (i + 2 < n) {
                    loadA2(b00, b01, jn, lane);
                    jn = (i + 3 < n) ? psec[p0 + i + 3] : 0;
                }
                if (++i >= n) break;
                process_pair(b10, b11, p0 + i);
                if (i + 2 < n) {
                    loadA2(b10, b11, jn, lane);
                    jn = (i + 3 < n) ? psec[p0 + i + 3] : 0;
                }
                if (++i >= n) break;
            }
        }

        // invariants
        const float inv0 = acc0;
        const float inv1 = acc1 * acc1 + acc2 * acc2 + acc3 * acc3;

        // GroupNorm over 32 lanes per group
        const float m0 = warp_sum(inv0) * (1.f / 32.f);
        const float m1 = warp_sum(inv1) * (1.f / 32.f);
        const float c0 = inv0 - m0;
        const float c1 = inv1 - m1;
        const float v0s = warp_sum(c0 * c0) * (1.f / 32.f);
        const float v1s = warp_sum(c1 * c1) * (1.f / 32.f);
        float xn0 = c0 * rsqrtf(v0s + GN_EPS);
        float xn1 = c1 * rsqrtf(v1s + GN_EPS);
        xn0 = fmaf(xn0, gw0, gb0);
        xn1 = fmaf(xn1, gw1, gb1);

        // mixing (weights from smem) + self
        float oa = g_self[(size_t)a * NF + lane];
        float ob = 0.f;
#pragma unroll
        for (int oin = 0; oin < 32; ++oin) {
            const float n0 = __shfl_sync(0xffffffffu, xn0, oin);
            const float n1 = __shfl_sync(0xffffffffu, xn1, oin);
            oa = fmaf(n0, msh[(oin * 2 + 0) * NF + lane], oa);
            ob = fmaf(n1, msh[(oin * 2 + 1) * NF + lane], ob);
        }
        out[(size_t)a * NF + lane] = oa + ob;

        a = __shfl_sync(0xffffffffu, an, 0);
    }
}

// ---------------------------------------------------------------------------
extern "C" void kernel_launch(void* const* d_in, const int* in_sizes, int n_in,
                              void* d_out, int out_size) {
    const float* in_features = (const float*)d_in[0];
    const float* tensor_rhats = (const float*)d_in[1];
    const float* dist_pairs = (const float*)d_in[2];
    const float* int_weights = (const float*)d_in[3];
    const float* selfint_w = (const float*)d_in[4];
    const float* selfint_b = (const float*)d_in[5];
    const float* mixing_weights = (const float*)d_in[6];
    const float* gn_weight = (const float*)d_in[7];
    const float* gn_bias = (const float*)d_in[8];
    const float* sens_mu = (const float*)d_in[9];
    const float* sens_sigma = (const float*)d_in[10];
    const int* pair_first = (const int*)d_in[11];
    const int* pair_second = (const int*)d_in[12];
    float* out = (float*)d_out;

    k_fused<<<NB, NT>>>(in_features, tensor_rhats, dist_pairs, int_weights,
                        selfint_w, selfint_b, mixing_weights, gn_weight,
                        gn_bias, sens_mu, sens_sigma, pair_first, pair_second,
                        out);
}

// round 16
// speedup vs baseline: 1.0161x; 1.0161x over previous
#include <cuda_runtime.h>
#include <cuda_fp16.h>
#include <cstdint>

#define N_ATOMS 8000
#define N_PAIRS 80000
#define NF 32
#define GN_EPS 1e-5f

#define NB 500            // 4 CTAs/SM (64-reg budget): all resident, and
                          // 2000 tiles / 8000 atoms / 40000 sense chunks
                          // all divide exactly
#define NT 256
#define NWARPS_TOT (NB * 8)   // 4000 warps

// Scratch (device globals: no allocation allowed)
// A-table fp16, o-major: A2[a*256 + o*8 + q] = half2( A[a,2q,o], A[a,2q+1,o] )
__device__ __align__(16) uint32_t g_A2[(size_t)N_ATOMS * 256];
// fp16 sense: sense2[p*8 + q] = half2( sense[p,2q], sense[p,2q+1] )
__device__ __align__(16) uint32_t g_sense2[(size_t)N_PAIRS * 8];
__device__ __align__(16) float g_self[(size_t)N_ATOMS * NF];
__device__ int g_seg[N_ATOMS + 1];

// Grid barrier state: monotonic across launches (deterministic, no reset).
__device__ unsigned long long g_arrive = 0;
__device__ volatile unsigned long long g_release = 0;

__device__ __forceinline__ void grid_barrier() {
    __syncthreads();
    if (threadIdx.x == 0) {
        __threadfence();
        unsigned long long t = atomicAdd(&g_arrive, 1ULL) + 1ULL;
        unsigned long long target = ((t + NB - 1) / NB) * NB;
        if (t == target) {
            g_release = target;
        } else {
            while (g_release < target) __nanosleep(64);   // fixed: no backoff
        }
        __threadfence();
    }
    __syncthreads();
}

__device__ __forceinline__ float warp_sum(float v) {
#pragma unroll
    for (int off = 16; off; off >>= 1)
        v += __shfl_xor_sync(0xffffffffu, v, off);
    return v;
}

// A row gather: 2x LDG.128 (lane = o), 32B per lane
__device__ __forceinline__ void loadA2(uint4& u0, uint4& u1, int j, int lane) {
    const uint4* base = (const uint4*)(g_A2 + (size_t)j * 256 + lane * 8);
    u0 = __ldg(base);
    u1 = __ldg(base + 1);
}

__global__ void __launch_bounds__(NT, 4) k_fused(
    const float* __restrict__ feat,     // (N,32)
    const float* __restrict__ rhats,    // (P,4)
    const float* __restrict__ dist,     // (P,)
    const float* __restrict__ Wint,     // (16,32,32) d,o,f
    const float* __restrict__ sw,       // (32,32) o,f
    const float* __restrict__ sb,       // (32,)
    const float* __restrict__ mw,       // (64,32)
    const float* __restrict__ gnw,      // (64,)
    const float* __restrict__ gnb,      // (64,)
    const float* __restrict__ mu,       // (16,)
    const float* __restrict__ sg,       // (16,)
    const int*   __restrict__ pf,       // (P,)  sorted
    const int*   __restrict__ psec,     // (P,)
    float* __restrict__ out)            // (N,32)
{
    __shared__ __align__(16) float swT[NF * NF];       // selfint weights^T (4KB)
    __shared__ __align__(16) float msh[64 * NF];       // mixing weights (8KB)
    __shared__ __align__(16) float fsh[4 * NF];        // feat staging (0.5KB)
    __shared__ __align__(16) uint32_t WTs[32 * 257];   // fp16 Wint^T pad (33KB)

    const int tid  = threadIdx.x;
    const int bid  = blockIdx.x;
    const int lane = tid & 31;
    const int wid  = tid >> 5;
    const int gtid  = bid * NT + tid;
    const int gwarp = bid * 8 + wid;

    // per-lane constants
    const float mu_l  = mu[lane & 15];
    const float isg_l = 1.0f / sg[lane & 15];
    const float gw0 = gnw[lane],      gb0 = gnb[lane];
    const float gw1 = gnw[32 + lane], gb1 = gnb[32 + lane];

    // ======================= PHASE A (block-local; no internal barrier) =====
    // stage smem tables (all coalesced)
    for (int i = tid; i < 64 * NF; i += NT) msh[i] = mw[i];
    for (int i = tid; i < NF * NF; i += NT) {
        int o = i >> 5, f = i & 31;
        swT[f * NF + o] = sw[i];
    }
    // per-block transposed fp16 weight table: WTs[f*257 + q*32+o]
    {
#pragma unroll
        for (int cc = 0; cc < 32; ++cc) {
            float wa = Wint[(2 * wid) * (NF * NF) + cc * NF + lane];
            float wb = Wint[(2 * wid + 1) * (NF * NF) + cc * NF + lane];
            __half2 h2 = __floats2half2_rn(wa, wb);
            WTs[lane * 257 + wid * 32 + cc] = *reinterpret_cast<uint32_t*>(&h2);
        }
    }
    __syncthreads();

    // A.seg: segment starts via scatter on sorted pair_first
    for (int p = gtid; p < N_PAIRS; p += NB * NT) {
        int cur  = pf[p];
        int prev = (p == 0) ? -1 : pf[p - 1];
        for (int a = prev + 1; a <= cur; ++a) g_seg[a] = p;
        if (p == N_PAIRS - 1)
            for (int a = cur + 1; a <= N_ATOMS; ++a) g_seg[a] = N_PAIRS;
    }

    // A.sense: fp16 sense table, warp-cooperative; exactly 10 chunks/warp
    {
        const int h = lane >> 4;
        const int d = lane & 15;
        for (int pb = gwarp * 2; pb < N_PAIRS; pb += NWARPS_TOT * 2) {
            const float dd = dist[pb + h];
            const float invd = 1.0f / dd;
            float cut = 0.f;
            if (dd < 6.5f) {
                float cc = cospif(dd * (0.5f / 6.5f));
                cut = cc * cc;
            }
            float t = (invd - mu_l) * isg_l;
            float e = cut * __expf(-0.5f * t * t);
            float e_hi = __shfl_xor_sync(0xffffffffu, e, 1);  // partner d^1
            if ((d & 1) == 0) {
                __half2 h2 = __floats2half2_rn(e, e_hi);
                g_sense2[(size_t)pb * 8 + h * 8 + (d >> 1)] =
                    *reinterpret_cast<uint32_t*>(&h2);
            }
        }
    }

    // A.self: self-interaction (fp32); exactly 2 rows/thread
    for (int idx = gtid; idx < N_ATOMS * NF; idx += NB * NT) {
        int a = idx >> 5, o = idx & 31;
        float s = sb[o];
        const float* fr = feat + (size_t)a * NF;
#pragma unroll
        for (int f = 0; f < NF; ++f)
            s = fmaf(fr[f], swT[f * NF + o], s);
        g_self[idx] = s;
    }

    // A.gemm: A-table, 4-atom tiles (64-reg friendly); exactly 4 tiles/block
    {
        const int c = wid * 32 + lane;       // q = wid, o = lane
        const float4* fsh4 = (const float4*)fsh;
        for (int tile = bid; tile < N_ATOMS / 4; tile += NB) {
            const int a0 = tile * 4;
            __syncthreads();
            if (tid < 4 * NF) fsh[tid] = feat[(size_t)a0 * NF + tid];
            __syncthreads();
            float accA[4], accB[4];
#pragma unroll
            for (int k = 0; k < 4; ++k) { accA[k] = 0.f; accB[k] = 0.f; }
#pragma unroll
            for (int f4 = 0; f4 < 8; ++f4) {
                float2 wf[4];
#pragma unroll
                for (int t = 0; t < 4; ++t) {
                    uint32_t w2 = WTs[(4 * f4 + t) * 257 + c];
                    wf[t] = __half22float2(*reinterpret_cast<__half2*>(&w2));
                }
#pragma unroll
                for (int k = 0; k < 4; ++k) {
                    float4 v = fsh4[k * 8 + f4];
                    accA[k] = fmaf(v.x, wf[0].x, accA[k]);
                    accB[k] = fmaf(v.x, wf[0].y, accB[k]);
                    accA[k] = fmaf(v.y, wf[1].x, accA[k]);
                    accB[k] = fmaf(v.y, wf[1].y, accB[k]);
                    accA[k] = fmaf(v.z, wf[2].x, accA[k]);
                    accB[k] = fmaf(v.z, wf[2].y, accB[k]);
                    accA[k] = fmaf(v.w, wf[3].x, accA[k]);
                    accB[k] = fmaf(v.w, wf[3].y, accB[k]);
                }
            }
#pragma unroll
            for (int k = 0; k < 4; ++k) {
                __half2 h2 = __floats2half2_rn(accA[k], accB[k]);
                g_A2[(size_t)(a0 + k) * 256 + lane * 8 + wid] =
                    *reinterpret_cast<uint32_t*>(&h2);
            }
        }
    }

    grid_barrier();    // the ONLY grid barrier

    // ============================ PHASE B ===================================
    // static warp-per-atom: exactly 2 atoms per warp; even/odd double buffer
    for (int a = gwarp; a < N_ATOMS; a += NWARPS_TOT) {
        const int p0 = g_seg[a];
        const int n  = g_seg[a + 1] - p0;

        float acc0 = 0.f, acc1 = 0.f, acc2 = 0.f, acc3 = 0.f;

        auto process_pair = [&](const uint4& u0, const uint4& u1, int p) {
            const uint4* sp = (const uint4*)(g_sense2 + 8 * (size_t)p);
            uint4 s0 = __ldg(sp);
            uint4 s1 = __ldg(sp + 1);
            const float4 rh = *(const float4*)(rhats + 4 * (size_t)p);
            float dA = 0.f, dB = 0.f;
            {
                const uint32_t* sv = (const uint32_t*)&s0;
                const uint32_t* av = (const uint32_t*)&u0;
#pragma unroll
                for (int q = 0; q < 4; ++q) {
                    float2 fs = __half22float2(*(const __half2*)(&sv[q]));
                    float2 fa = __half22float2(*(const __half2*)(&av[q]));
                    dA = fmaf(fs.x, fa.x, dA);
                    dB = fmaf(fs.y, fa.y, dB);
                }
            }
            {
                const uint32_t* sv = (const uint32_t*)&s1;
                const uint32_t* av = (const uint32_t*)&u1;
#pragma unroll
                for (int q = 0; q < 4; ++q) {
                    float2 fs = __half22float2(*(const __half2*)(&sv[q]));
                    float2 fa = __half22float2(*(const __half2*)(&av[q]));
                    dA = fmaf(fs.x, fa.x, dA);
                    dB = fmaf(fs.y, fa.y, dB);
                }
            }
            const float wgt = dA + dB;
            acc0 = fmaf(rh.x, wgt, acc0);
            acc1 = fmaf(rh.y, wgt, acc1);
            acc2 = fmaf(rh.z, wgt, acc2);
            acc3 = fmaf(rh.w, wgt, acc3);
        };

        if (n > 0) {
            uint4 b00, b01, b10, b11;
            loadA2(b00, b01, psec[p0], lane);
            if (n > 1) loadA2(b10, b11, psec[p0 + 1], lane);
            int jn = (n > 2) ? psec[p0 + 2] : 0;
            int i = 0;
            for (;;) {
                process_pair(b00, b01, p0 + i);
                if (i + 2 < n) {
                    loadA2(b00, b01, jn, lane);
                    jn = (i + 3 < n) ? psec[p0 + i + 3] : 0;
                }
                if (++i >= n) break;
                process_pair(b10, b11, p0 + i);
                if (i + 2 < n) {
                    loadA2(b10, b11, jn, lane);
                    jn = (i + 3 < n) ? psec[p0 + i + 3] : 0;
                }
                if (++i >= n) break;
            }
        }

        // invariants
        const float inv0 = acc0;
        const float inv1 = acc1 * acc1 + acc2 * acc2 + acc3 * acc3;

        // GroupNorm over 32 lanes per group
        const float m0 = warp_sum(inv0) * (1.f / 32.f);
        const float m1 = warp_sum(inv1) * (1.f / 32.f);
        const float c0 = inv0 - m0;
        const float c1 = inv1 - m1;
        const float v0s = warp_sum(c0 * c0) * (1.f / 32.f);
        const float v1s = warp_sum(c1 * c1) * (1.f / 32.f);
        float xn0 = c0 * rsqrtf(v0s + GN_EPS);
        float xn1 = c1 * rsqrtf(v1s + GN_EPS);
        xn0 = fmaf(xn0, gw0, gb0);
        xn1 = fmaf(xn1, gw1, gb1);

        // mixing (weights from smem) + self
        float oa = g_self[(size_t)a * NF + lane];
        float ob = 0.f;
#pragma unroll
        for (int oin = 0; oin < 32; ++oin) {
            const float n0 = __shfl_sync(0xffffffffu, xn0, oin);
            const float n1 = __shfl_sync(0xffffffffu, xn1, oin);
            oa = fmaf(n0, msh[(oin * 2 + 0) * NF + lane], oa);
            ob = fmaf(n1, msh[(oin * 2 + 1) * NF + lane], ob);
        }
        out[(size_t)a * NF + lane] = oa + ob;
    }
}

// ---------------------------------------------------------------------------
extern "C" void kernel_launch(void* const* d_in, const int* in_sizes, int n_in,
                              void* d_out, int out_size) {
    const float* in_features = (const float*)d_in[0];
    const float* tensor_rhats = (const float*)d_in[1];
    const float* dist_pairs = (const float*)d_in[2];
    const float* int_weights = (const float*)d_in[3];
    const float* selfint_w = (const float*)d_in[4];
    const float* selfint_b = (const float*)d_in[5];
    const float* mixing_weights = (const float*)d_in[6];
    const float* gn_weight = (const float*)d_in[7];
    const float* gn_bias = (const float*)d_in[8];
    const float* sens_mu = (const float*)d_in[9];
    const float* sens_sigma = (const float*)d_in[10];
    const int* pair_first = (const int*)d_in[11];
    const int* pair_second = (const int*)d_in[12];
    float* out = (float*)d_out;

    k_fused<<<NB, NT>>>(in_features, tensor_rhats, dist_pairs, int_weights,
                        selfint_w, selfint_b, mixing_weights, gn_weight,
                        gn_bias, sens_mu, sens_sigma, pair_first, pair_second,
                        out);
}

// round 17
// speedup vs baseline: 1.1659x; 1.1474x over previous
#include <cuda_runtime.h>
#include <cuda_fp16.h>
#include <cstdint>

#define N_ATOMS 8000
#define N_PAIRS 80000
#define NF 32
#define GN_EPS 1e-5f

#define NB 444            // 3 CTAs/SM x 148 SMs: all resident in wave 1
#define NT 256
#define NWARPS_TOT (NB * 8)

// Scratch (device globals: no allocation allowed)
// A-table fp16, gather-optimal layout: row a is 256 u32; lane l's data at
// u32 idx {4l..4l+3} (q=0..3) and {128+4l..128+4l+3} (q=4..7).
// Each uint4 load by a warp is contiguous (512B span = 4 wavefronts).
__device__ __align__(16) uint32_t g_A2[(size_t)N_ATOMS * 256];
// fp16 sense: sense2[p*8 + q] = half2( sense[p,2q], sense[p,2q+1] )
__device__ __align__(16) uint32_t g_sense2[(size_t)N_PAIRS * 8];
__device__ __align__(16) float g_self[(size_t)N_ATOMS * NF];
__device__ int g_seg[N_ATOMS + 1];

// Grid barrier state: monotonic across launches (deterministic, no reset).
__device__ unsigned long long g_arrive = 0;
__device__ volatile unsigned long long g_release = 0;

__device__ __forceinline__ void grid_barrier() {
    __syncthreads();
    if (threadIdx.x == 0) {
        __threadfence();
        unsigned long long t = atomicAdd(&g_arrive, 1ULL) + 1ULL;
        unsigned long long target = ((t + NB - 1) / NB) * NB;
        if (t == target) {
            g_release = target;
        } else {
            while (g_release < target) __nanosleep(64);   // fixed: no backoff
        }
        __threadfence();
    }
    __syncthreads();
}

__device__ __forceinline__ float warp_sum(float v) {
#pragma unroll
    for (int off = 16; off; off >>= 1)
        v += __shfl_xor_sync(0xffffffffu, v, off);
    return v;
}

// A row gather: 2x fully-contiguous LDG.128 (4 wavefronts each, min possible)
__device__ __forceinline__ void loadA2(uint4& u0, uint4& u1, int j, int lane) {
    const uint4* base = (const uint4*)(g_A2 + (size_t)j * 256);
    u0 = __ldg(base + lane);        // u32s [4*lane .. 4*lane+3]   (q = 0..3)
    u1 = __ldg(base + 32 + lane);   // u32s [128+4*lane .. +3]     (q = 4..7)
}

__global__ void __launch_bounds__(NT, 3) k_fused(
    const float* __restrict__ feat,     // (N,32)
    const float* __restrict__ rhats,    // (P,4)
    const float* __restrict__ dist,     // (P,)
    const float* __restrict__ Wint,     // (16,32,32) d,o,f
    const float* __restrict__ sw,       // (32,32) o,f
    const float* __restrict__ sb,       // (32,)
    const float* __restrict__ mw,       // (64,32)
    const float* __restrict__ gnw,      // (64,)
    const float* __restrict__ gnb,      // (64,)
    const float* __restrict__ mu,       // (16,)
    const float* __restrict__ sg,       // (16,)
    const int*   __restrict__ pf,       // (P,)  sorted
    const int*   __restrict__ psec,     // (P,)
    float* __restrict__ out)            // (N,32)
{
    __shared__ __align__(16) float swT[NF * NF];       // selfint weights^T (4KB)
    __shared__ __align__(16) float msh[64 * NF];       // mixing weights (8KB)
    __shared__ __align__(16) float fsh[8 * NF];        // feat staging (1KB)
    __shared__ __align__(16) uint32_t WTs[32 * 257];   // fp16 Wint^T pad (33KB)

    const int tid  = threadIdx.x;
    const int bid  = blockIdx.x;
    const int lane = tid & 31;
    const int wid  = tid >> 5;
    const int gtid  = bid * NT + tid;
    const int gwarp = bid * 8 + wid;

    // per-lane constants
    const float mu_l  = mu[lane & 15];
    const float isg_l = 1.0f / sg[lane & 15];
    const float gw0 = gnw[lane],      gb0 = gnb[lane];
    const float gw1 = gnw[32 + lane], gb1 = gnb[32 + lane];

    // ======================= PHASE A (block-local; no internal barrier) =====
    // stage smem tables (all coalesced)
    for (int i = tid; i < 64 * NF; i += NT) msh[i] = mw[i];
    for (int i = tid; i < NF * NF; i += NT) {
        int o = i >> 5, f = i & 31;
        swT[f * NF + o] = sw[i];
    }
    // per-block transposed fp16 weight table: WTs[f*257 + q*32+o]
    {
#pragma unroll
        for (int cc = 0; cc < 32; ++cc) {
            float wa = Wint[(2 * wid) * (NF * NF) + cc * NF + lane];
            float wb = Wint[(2 * wid + 1) * (NF * NF) + cc * NF + lane];
            __half2 h2 = __floats2half2_rn(wa, wb);
            WTs[lane * 257 + wid * 32 + cc] = *reinterpret_cast<uint32_t*>(&h2);
        }
    }
    __syncthreads();

    // A.seg: segment starts via scatter on sorted pair_first
    for (int p = gtid; p < N_PAIRS; p += NB * NT) {
        int cur  = pf[p];
        int prev = (p == 0) ? -1 : pf[p - 1];
        for (int a = prev + 1; a <= cur; ++a) g_seg[a] = p;
        if (p == N_PAIRS - 1)
            for (int a = cur + 1; a <= N_ATOMS; ++a) g_seg[a] = N_PAIRS;
    }

    // A.sense: fp16 sense table, warp-cooperative. lane = h*16 + d, pair pb+h.
    {
        const int h = lane >> 4;
        const int d = lane & 15;
        for (int pb = gwarp * 2; pb < N_PAIRS; pb += NWARPS_TOT * 2) {
            const float dd = dist[pb + h];
            const float invd = 1.0f / dd;
            float cut = 0.f;
            if (dd < 6.5f) {
                float cc = cospif(dd * (0.5f / 6.5f));
                cut = cc * cc;
            }
            float t = (invd - mu_l) * isg_l;
            float e = cut * __expf(-0.5f * t * t);
            float e_hi = __shfl_xor_sync(0xffffffffu, e, 1);  // partner d^1
            if ((d & 1) == 0) {
                __half2 h2 = __floats2half2_rn(e, e_hi);
                g_sense2[(size_t)pb * 8 + h * 8 + (d >> 1)] =
                    *reinterpret_cast<uint32_t*>(&h2);
            }
        }
    }

    // A.self: self-interaction (fp32)
    for (int idx = gtid; idx < N_ATOMS * NF; idx += NB * NT) {
        int a = idx >> 5, o = idx & 31;
        float s = sb[o];
        const float* fr = feat + (size_t)a * NF;
#pragma unroll
        for (int f = 0; f < NF; ++f)
            s = fmaf(fr[f], swT[f * NF + o], s);
        g_self[idx] = s;
    }

    // A.gemm: A-table, 8-atom tiles, weights from smem WTs.
    // store offset: q<4 -> 4o+q ; q>=4 -> 128 + 4o + (q-4)   (gather-optimal)
    {
        const int c = wid * 32 + lane;       // q = wid, o = lane
        const int stoff = (wid < 4) ? (lane * 4 + wid)
                                    : (128 + lane * 4 + (wid - 4));
        const float4* fsh4 = (const float4*)fsh;
        for (int tile = bid; tile < N_ATOMS / 8; tile += NB) {
            const int a0 = tile * 8;
            __syncthreads();
            fsh[tid] = feat[(size_t)a0 * NF + tid];
            __syncthreads();
            float accA[8], accB[8];
#pragma unroll
            for (int k = 0; k < 8; ++k) { accA[k] = 0.f; accB[k] = 0.f; }
#pragma unroll
            for (int f4 = 0; f4 < 8; ++f4) {
                float2 wf[4];
#pragma unroll
                for (int t = 0; t < 4; ++t) {
                    uint32_t w2 = WTs[(4 * f4 + t) * 257 + c];
                    wf[t] = __half22float2(*reinterpret_cast<__half2*>(&w2));
                }
#pragma unroll
                for (int k = 0; k < 8; ++k) {
                    float4 v = fsh4[k * 8 + f4];
                    accA[k] = fmaf(v.x, wf[0].x, accA[k]);
                    accB[k] = fmaf(v.x, wf[0].y, accB[k]);
                    accA[k] = fmaf(v.y, wf[1].x, accA[k]);
                    accB[k] = fmaf(v.y, wf[1].y, accB[k]);
                    accA[k] = fmaf(v.z, wf[2].x, accA[k]);
                    accB[k] = fmaf(v.z, wf[2].y, accB[k]);
                    accA[k] = fmaf(v.w, wf[3].x, accA[k]);
                    accB[k] = fmaf(v.w, wf[3].y, accB[k]);
                }
            }
#pragma unroll
            for (int k = 0; k < 8; ++k) {
                __half2 h2 = __floats2half2_rn(accA[k], accB[k]);
                g_A2[(size_t)(a0 + k) * 256 + stoff] =
                    *reinterpret_cast<uint32_t*>(&h2);
            }
        }
    }

    grid_barrier();    // the ONLY grid barrier

    // ============================ PHASE B ===================================
    // static warp-per-atom grid-stride; even/odd double buffer.
    for (int a = gwarp; a < N_ATOMS; a += NWARPS_TOT) {
        const int p0 = g_seg[a];
        const int n  = g_seg[a + 1] - p0;

        float acc0 = 0.f, acc1 = 0.f, acc2 = 0.f, acc3 = 0.f;

        auto process_pair = [&](const uint4& u0, const uint4& u1, int p) {
            const uint4* sp = (const uint4*)(g_sense2 + 8 * (size_t)p);
            uint4 s0 = __ldg(sp);       // q = 0..3
            uint4 s1 = __ldg(sp + 1);   // q = 4..7
            const float4 rh = *(const float4*)(rhats + 4 * (size_t)p);
            float dA = 0.f, dB = 0.f;
            {
                const uint32_t* sv = (const uint32_t*)&s0;
                const uint32_t* av = (const uint32_t*)&u0;
#pragma unroll
                for (int q = 0; q < 4; ++q) {
                    float2 fs = __half22float2(*(const __half2*)(&sv[q]));
                    float2 fa = __half22float2(*(const __half2*)(&av[q]));
                    dA = fmaf(fs.x, fa.x, dA);
                    dB = fmaf(fs.y, fa.y, dB);
                }
            }
            {
                const uint32_t* sv = (const uint32_t*)&s1;
                const uint32_t* av = (const uint32_t*)&u1;
#pragma unroll
                for (int q = 0; q < 4; ++q) {
                    float2 fs = __half22float2(*(const __half2*)(&sv[q]));
                    float2 fa = __half22float2(*(const __half2*)(&av[q]));
                    dA = fmaf(fs.x, fa.x, dA);
                    dB = fmaf(fs.y, fa.y, dB);
                }
            }
            const float wgt = dA + dB;
            acc0 = fmaf(rh.x, wgt, acc0);
            acc1 = fmaf(rh.y, wgt, acc1);
            acc2 = fmaf(rh.z, wgt, acc2);
            acc3 = fmaf(rh.w, wgt, acc3);
        };

        if (n > 0) {
            uint4 b00, b01, b10, b11;
            loadA2(b00, b01, psec[p0], lane);
            if (n > 1) loadA2(b10, b11, psec[p0 + 1], lane);
            int jn = (n > 2) ? psec[p0 + 2] : 0;
            int i = 0;
            for (;;) {
                process_pair(b00, b01, p0 + i);
                if (i + 2 < n) {
                    loadA2(b00, b01, jn, lane);
                    jn = (i + 3 < n) ? psec[p0 + i + 3] : 0;
                }
                if (++i >= n) break;
                process_pair(b10, b11, p0 + i);
                if (i + 2 < n) {
                    loadA2(b10, b11, jn, lane);
                    jn = (i + 3 < n) ? psec[p0 + i + 3] : 0;
                }
                if (++i >= n) break;
            }
        }

        // invariants
        const float inv0 = acc0;
        const float inv1 = acc1 * acc1 + acc2 * acc2 + acc3 * acc3;

        // GroupNorm over 32 lanes per group
        const float m0 = warp_sum(inv0) * (1.f / 32.f);
        const float m1 = warp_sum(inv1) * (1.f / 32.f);
        const float c0 = inv0 - m0;
        const float c1 = inv1 - m1;
        const float v0s = warp_sum(c0 * c0) * (1.f / 32.f);
        const float v1s = warp_sum(c1 * c1) * (1.f / 32.f);
        float xn0 = c0 * rsqrtf(v0s + GN_EPS);
        float xn1 = c1 * rsqrtf(v1s + GN_EPS);
        xn0 = fmaf(xn0, gw0, gb0);
        xn1 = fmaf(xn1, gw1, gb1);

        // mixing (weights from smem) + self
        float oa = g_self[(size_t)a * NF + lane];
        float ob = 0.f;
#pragma unroll
        for (int oin = 0; oin < 32; ++oin) {
            const float n0 = __shfl_sync(0xffffffffu, xn0, oin);
            const float n1 = __shfl_sync(0xffffffffu, xn1, oin);
            oa = fmaf(n0, msh[(oin * 2 + 0) * NF + lane], oa);
            ob = fmaf(n1, msh[(oin * 2 + 1) * NF + lane], ob);
        }
        out[(size_t)a * NF + lane] = oa + ob;
    }
}

// ---------------------------------------------------------------------------
extern "C" void kernel_launch(void* const* d_in, const int* in_sizes, int n_in,
                              void* d_out, int out_size) {
    const float* in_features = (const float*)d_in[0];
    const float* tensor_rhats = (const float*)d_in[1];
    const float* dist_pairs = (const float*)d_in[2];
    const float* int_weights = (const float*)d_in[3];
    const float* selfint_w = (const float*)d_in[4];
    const float* selfint_b = (const float*)d_in[5];
    const float* mixing_weights = (const float*)d_in[6];
    const float* gn_weight = (const float*)d_in[7];
    const float* gn_bias = (const float*)d_in[8];
    const float* sens_mu = (const float*)d_in[9];
    const float* sens_sigma = (const float*)d_in[10];
    const int* pair_first = (const int*)d_in[11];
    const int* pair_second = (const int*)d_in[12];
    float* out = (float*)d_out;

    k_fused<<<NB, NT>>>(in_features, tensor_rhats, dist_pairs, int_weights,
                        selfint_w, selfint_b, mixing_weights, gn_weight,
                        gn_bias, sens_mu, sens_sigma, pair_first, pair_second,
                        out);
}